// round 12
// baseline (speedup 1.0000x reference)
#include <cuda_runtime.h>
#include <cuda_bf16.h>
#include <math.h>
#include <stdint.h>

// ---------------- Problem constants ----------------
#define BATCH 16384
#define NFEAT 39
#define EMB   16
#define HID   200
#define NPAD  208           // padded N (and K) for 16/8 tiling
#define NKSG  27            // total ksteps: L0:1, L1:13, L2:13
#define NTILE 26            // n8 tiles per layer

// ---------------- Scratch ----------------
// Weights pre-packed in mma fragment order:
// [ksg (27)][ntile (26)][lane (32)] x uint4 {bh0, bh1, bl0, bl1}
__device__ uint4 g_wfrag[NKSG * NTILE * 32];

// =====================================================================
// Helpers
// =====================================================================
__device__ __forceinline__ uint32_t smem_u32(const void* p) {
    uint32_t a;
    asm("{ .reg .u64 t; cvta.to.shared.u64 t, %1; cvt.u32.u64 %0, t; }"
        : "=r"(a) : "l"(p));
    return a;
}
__device__ __forceinline__ void ldsm4(uint32_t addr, uint32_t* r) {
    asm volatile("ldmatrix.sync.aligned.m8n8.x4.shared.b16 {%0,%1,%2,%3}, [%4];"
                 : "=r"(r[0]), "=r"(r[1]), "=r"(r[2]), "=r"(r[3]) : "r"(addr));
}
__device__ __forceinline__ void mma16816(float* c, const uint32_t* a,
                                         uint32_t b0, uint32_t b1) {
    asm volatile("mma.sync.aligned.m16n8k16.row.col.f32.bf16.bf16.f32 "
                 "{%0,%1,%2,%3}, {%4,%5,%6,%7}, {%8,%9}, {%0,%1,%2,%3};"
                 : "+f"(c[0]), "+f"(c[1]), "+f"(c[2]), "+f"(c[3])
                 : "r"(a[0]), "r"(a[1]), "r"(a[2]), "r"(a[3]),
                   "r"(b0), "r"(b1));
}
__device__ __forceinline__ void split_pack(float x0, float x1,
                                           unsigned& wh, unsigned& wl) {
    __nv_bfloat16 h0 = __float2bfloat16_rn(x0);
    __nv_bfloat16 h1 = __float2bfloat16_rn(x1);
    float r0 = x0 - __bfloat162float(h0);
    float r1 = x1 - __bfloat162float(h1);
    __nv_bfloat16 l0 = __float2bfloat16_rn(r0);
    __nv_bfloat16 l1 = __float2bfloat16_rn(r1);
    wh = ((unsigned)__bfloat16_as_ushort(h1) << 16) | __bfloat16_as_ushort(h0);
    wl = ((unsigned)__bfloat16_as_ushort(l1) << 16) | __bfloat16_as_ushort(l0);
}
__device__ __forceinline__ void bar_pair(int pair) {
    asm volatile("bar.sync %0, 64;" :: "r"(1 + pair) : "memory");
}

// =====================================================================
// Kernel 1: weight fragment prep only (small, fast)
// =====================================================================
#define PREP_ITEMS (NKSG * NTILE * 32)          // 22464
#define PREP_BLOCKS ((PREP_ITEMS + 255) / 256)  // 88

__global__ __launch_bounds__(256, 1) void prep_kernel(
    const float* __restrict__ w0,
    const float* __restrict__ w1,
    const float* __restrict__ w2)
{
    const int g = blockIdx.x * 256 + threadIdx.x;
    if (g >= PREP_ITEMS) return;
    const int ksg   = g / (NTILE * 32);
    const int rem   = g - ksg * (NTILE * 32);
    const int ntile = rem >> 5;
    const int lane  = rem & 31;
    const int l  = (ksg == 0) ? 0 : (ksg <= 13) ? 1 : 2;
    const int s  = (ksg == 0) ? 0 : (ksg <= 13) ? (ksg - 1) : (ksg - 14);
    const int Kl = (l == 0) ? EMB : HID;
    const float* W = (l == 0) ? w0 : (l == 1) ? w1 : w2;

    const int n  = ntile * 8 + (lane >> 2);
    const int k0 = s * 16 + (lane & 3) * 2;

    float e0 = 0.f, e1 = 0.f, e2 = 0.f, e3 = 0.f;
    if (n < HID) {
        if (k0     < Kl) e0 = __ldg(W + (size_t)k0       * HID + n);
        if (k0 + 1 < Kl) e1 = __ldg(W + (size_t)(k0 + 1) * HID + n);
        if (k0 + 8 < Kl) e2 = __ldg(W + (size_t)(k0 + 8) * HID + n);
        if (k0 + 9 < Kl) e3 = __ldg(W + (size_t)(k0 + 9) * HID + n);
    }
    uint4 o;
    split_pack(e0, e1, o.x, o.z);
    split_pack(e2, e3, o.y, o.w);
    g_wfrag[g] = o;
}

// =====================================================================
// Kernel 2: fused embed + FM + split-bf16 mma.sync MLP + sigmoid.
// 64 rows/CTA, 256 threads (4 independent 64-thread pairs), 2 CTAs/SM.
// Blocked-N groups (5/4/4 n8-tiles) with As ping-pong buffers.
// =====================================================================
#define NTH2 256
#define ROWS 64
#define APB  432                 // As row pitch in bytes (27 x 16B, odd -> ldsm-clean)
#define AS0_H 0
#define AS0_L (ROWS * APB)                   // 27648
#define AS1_H (2 * ROWS * APB)               // 55296
#define AS1_L (3 * ROWS * APB)               // 82944
#define BIAS_O (4 * ROWS * APB)              // 110592
#define RSUM_O (BIAS_O + 3 * NPAD * 4)       // 113088
#define LR_O   (RSUM_O + ROWS * 4)           // 113344
#define SMEM_TOT (LR_O + ROWS * 4)           // 113600

// ---- one blocked-N group of MMAs ----
template<int NT>
__device__ __forceinline__ void mma_group(
    float (&acc)[5][4], const int ksteps, const int ksbase, const int ntbase,
    const uint32_t aH, const uint32_t aL, const uint32_t akofs, const int lane)
{
#pragma unroll
    for (int t = 0; t < NT; ++t)
#pragma unroll
        for (int q = 0; q < 4; ++q) acc[t][q] = 0.f;

#pragma unroll 2
    for (int ks = 0; ks < ksteps; ++ks) {
        uint32_t ah[4], al[4];
        const uint32_t ko = (uint32_t)(ks * 16) + akofs;
        ldsm4(aH + ko * 2, ah);
        ldsm4(aL + ko * 2, al);
        const uint4* bp = g_wfrag
            + ((size_t)(ksbase + ks) * NTILE + ntbase) * 32 + lane;
#pragma unroll
        for (int nt = 0; nt < NT; ++nt) {
            const uint4 f = __ldg(bp + nt * 32);
            mma16816(acc[nt], ah, f.x, f.y);   // A_hi * B_hi
            mma16816(acc[nt], ah, f.z, f.w);   // A_hi * B_lo
            mma16816(acc[nt], al, f.x, f.y);   // A_lo * B_hi
        }
    }
}

template<int NT>
__device__ __forceinline__ void epi_store(
    float (&acc)[5][4], char* smem, const uint32_t dH, const uint32_t dL,
    const float* __restrict__ bias, const int ntbase, const int pair, const int lane)
{
    const int r1 = pair * 16 + (lane >> 2);
#pragma unroll
    for (int nt = 0; nt < NT; ++nt) {
        const int n = (ntbase + nt) * 8 + 2 * (lane & 3);
        const float bb0 = bias[n];
        const float bb1 = bias[n + 1];
        unsigned wh, wl;
        split_pack(fmaxf(acc[nt][0] + bb0, 0.f),
                   fmaxf(acc[nt][1] + bb1, 0.f), wh, wl);
        *(unsigned*)(smem + dH + r1 * APB + 2 * n) = wh;
        *(unsigned*)(smem + dL + r1 * APB + 2 * n) = wl;
        split_pack(fmaxf(acc[nt][2] + bb0, 0.f),
                   fmaxf(acc[nt][3] + bb1, 0.f), wh, wl);
        *(unsigned*)(smem + dH + (r1 + 8) * APB + 2 * n) = wh;
        *(unsigned*)(smem + dL + (r1 + 8) * APB + 2 * n) = wl;
    }
}

template<int NT>
__device__ __forceinline__ void epi_rsum(
    float (&acc)[5][4], const float* __restrict__ bias,
    const int ntbase, const int lane, float& rs1, float& rs2)
{
#pragma unroll
    for (int nt = 0; nt < NT; ++nt) {
        const int n = (ntbase + nt) * 8 + 2 * (lane & 3);
        const float bb0 = bias[n];
        const float bb1 = bias[n + 1];
        rs1 += fmaxf(acc[nt][0] + bb0, 0.f) + fmaxf(acc[nt][1] + bb1, 0.f);
        rs2 += fmaxf(acc[nt][2] + bb0, 0.f) + fmaxf(acc[nt][3] + bb1, 0.f);
    }
}

__global__ __launch_bounds__(NTH2, 2) void nfm_fused_kernel(
    const int*   __restrict__ ids,
    const float* __restrict__ vals,
    const float* __restrict__ w,
    const float* __restrict__ v,
    const float* __restrict__ b0,
    const float* __restrict__ b1,
    const float* __restrict__ b2,
    const float* __restrict__ bglob,
    float*       __restrict__ out)
{
    extern __shared__ char smem[];
    const uint32_t SB = smem_u32(smem);
    float* bias_s = (float*)(smem + BIAS_O);
    float* rsum_s = (float*)(smem + RSUM_O);
    float* lr_s   = (float*)(smem + LR_O);

    const int tid   = threadIdx.x;
    const int wid   = tid >> 5;
    const int lane  = tid & 31;
    const int pair  = wid >> 1;              // 0..3
    const int nhalf = wid & 1;
    const int row0  = blockIdx.x * ROWS;

    // ---- init: bias + rsum (CTA-wide, once) ----
    for (int i = tid; i < 3 * NPAD; i += NTH2) {
        const int l = i / NPAD, n = i - l * NPAD;
        const float* bp = (l == 0) ? b0 : (l == 1) ? b1 : b2;
        bias_s[i] = (n < HID) ? __ldg(bp + n) : 0.f;
    }
    if (tid < ROWS) rsum_s[tid] = 0.f;
    __syncthreads();        // the only CTA-wide barrier

    // ---- fused embedding gather + FM: 4 lanes per row (lane = e-quad) ----
    {
        const int r8    = lane >> 2;         // 0..7 row within warp
        const int equad = lane & 3;          // e-quad 0..3
        const int r     = pair * 16 + nhalf * 8 + r8;
        const int gr    = row0 + r;
        const int*   idp = ids  + gr * NFEAT;
        const float* vp  = vals + gr * NFEAT;

        float4 xv = make_float4(0.f, 0.f, 0.f, 0.f);
        float4 x2 = make_float4(0.f, 0.f, 0.f, 0.f);
        float  lrw = 0.f;
#pragma unroll 13
        for (int f = 0; f < NFEAT; ++f) {
            const int   id  = __ldg(idp + f);
            const float val = __ldg(vp + f);
            const float4 ve = __ldg((const float4*)(v + (size_t)id * EMB) + equad);
            const float t0 = val * ve.x, t1 = val * ve.y;
            const float t2 = val * ve.z, t3 = val * ve.w;
            xv.x += t0; xv.y += t1; xv.z += t2; xv.w += t3;
            x2.x += t0 * t0; x2.y += t1 * t1;
            x2.z += t2 * t2; x2.w += t3 * t3;
            if (equad == 0) lrw += __ldg(w + id) * val;
        }
        const float fm0 = 0.5f * (xv.x * xv.x - x2.x);
        const float fm1 = 0.5f * (xv.y * xv.y - x2.y);
        const float fm2 = 0.5f * (xv.z * xv.z - x2.z);
        const float fm3 = 0.5f * (xv.w * xv.w - x2.w);
        unsigned h0, l0, h1, l1;
        split_pack(fm0, fm1, h0, l0);
        split_pack(fm2, fm3, h1, l1);
        *(uint2*)(smem + AS0_H + r * APB + equad * 8) = make_uint2(h0, h1);
        *(uint2*)(smem + AS0_L + r * APB + equad * 8) = make_uint2(l0, l1);
        if (equad == 0) lr_s[r] = lrw;
    }
    bar_pair(pair);          // pair's 16 rows of As buffer 0 ready

    // ---- MLP: 3 layers, blocked-N groups, As ping-pong ----
    float acc[5][4];
    float rs1 = 0.f, rs2 = 0.f;

    const uint32_t arow  = (uint32_t)(pair * 16 + (lane & 15));
    const uint32_t akofs = (uint32_t)((lane >> 4) << 3);
    const int nb = nhalf * 13;

    uint32_t curH = AS0_H, curL = AS0_L, nxtH = AS1_H, nxtL = AS1_L;

#pragma unroll 1
    for (int l = 0; l < 3; ++l) {
        const int ksteps = (l == 0) ? 1 : 13;
        const int ksbase = (l == 0) ? 0 : (l == 1) ? 1 : 14;
        const float* bias = bias_s + l * NPAD;
        const uint32_t aH = SB + curH + arow * APB;
        const uint32_t aL = SB + curL + arow * APB;

        if (l < 2) {
            mma_group<5>(acc, ksteps, ksbase, nb + 0, aH, aL, akofs, lane);
            epi_store<5>(acc, smem, nxtH, nxtL, bias, nb + 0, pair, lane);
            mma_group<4>(acc, ksteps, ksbase, nb + 5, aH, aL, akofs, lane);
            epi_store<4>(acc, smem, nxtH, nxtL, bias, nb + 5, pair, lane);
            mma_group<4>(acc, ksteps, ksbase, nb + 9, aH, aL, akofs, lane);
            epi_store<4>(acc, smem, nxtH, nxtL, bias, nb + 9, pair, lane);
        } else {
            mma_group<5>(acc, ksteps, ksbase, nb + 0, aH, aL, akofs, lane);
            epi_rsum<5>(acc, bias, nb + 0, lane, rs1, rs2);
            mma_group<4>(acc, ksteps, ksbase, nb + 5, aH, aL, akofs, lane);
            epi_rsum<4>(acc, bias, nb + 5, lane, rs1, rs2);
            mma_group<4>(acc, ksteps, ksbase, nb + 9, aH, aL, akofs, lane);
            epi_rsum<4>(acc, bias, nb + 9, lane, rs1, rs2);
        }
        bar_pair(pair);      // pair done: reads of cur + writes of nxt complete
        const uint32_t tH = curH; curH = nxtH; nxtH = tH;
        const uint32_t tL = curL; curL = nxtL; nxtL = tL;
    }

    // ---- row sums: 4-lane shfl reduce, pair-shared atomics, pair barrier ----
    rs1 += __shfl_xor_sync(0xffffffffu, rs1, 1);
    rs1 += __shfl_xor_sync(0xffffffffu, rs1, 2);
    rs2 += __shfl_xor_sync(0xffffffffu, rs2, 1);
    rs2 += __shfl_xor_sync(0xffffffffu, rs2, 2);
    if ((lane & 3) == 0) {
        const int r1 = pair * 16 + (lane >> 2);
        atomicAdd(&rsum_s[r1],     rs1);
        atomicAdd(&rsum_s[r1 + 8], rs2);
    }
    bar_pair(pair);

    if (nhalf == 0 && lane < 16) {
        const int r  = pair * 16 + lane;
        const int gr = row0 + r;
        const float x = lr_s[r] + __ldg(bglob) + rsum_s[r];
        out[gr] = 1.f / (1.f + expf(-x));
    }
}

// =====================================================================
// Launch
// =====================================================================
extern "C" void kernel_launch(void* const* d_in, const int* in_sizes, int n_in,
                              void* d_out, int out_size)
{
    const int*   feat_ids  = (const int*)  d_in[0];
    const float* feat_vals = (const float*)d_in[1];
    const float* w         = (const float*)d_in[2];
    const float* v         = (const float*)d_in[3];
    const float* b         = (const float*)d_in[4];
    const float* w0        = (const float*)d_in[5];
    const float* b0        = (const float*)d_in[6];
    const float* w1        = (const float*)d_in[7];
    const float* b1        = (const float*)d_in[8];
    const float* w2        = (const float*)d_in[9];
    const float* b2        = (const float*)d_in[10];
    float* out = (float*)d_out;

    prep_kernel<<<PREP_BLOCKS, 256>>>(w0, w1, w2);

    static bool attr_set = false;
    if (!attr_set) {
        cudaFuncSetAttribute(nfm_fused_kernel,
                             cudaFuncAttributeMaxDynamicSharedMemorySize,
                             SMEM_TOT);
        attr_set = true;
    }
    nfm_fused_kernel<<<BATCH / ROWS, NTH2, SMEM_TOT>>>(
        feat_ids, feat_vals, w, v, b0, b1, b2, b, out);
}

// round 13
// speedup vs baseline: 1.2090x; 1.2090x over previous
#include <cuda_runtime.h>
#include <cuda_bf16.h>
#include <math.h>
#include <stdint.h>

// ---------------- Problem constants ----------------
#define BATCH 16384
#define NFEAT 39
#define EMB   16
#define HID   200
#define NPAD  208           // padded N (and K) for 16/8 tiling
#define NKSG  27            // total ksteps: L0:1, L1:13, L2:13
#define NTILE 26            // n8 tiles per layer

// ---------------- Scratch ----------------
// Weights pre-packed in mma fragment order:
// [ksg (27)][ntile (26)][lane (32)] x uint4 {bh0, bh1, bl0, bl1}
__device__ uint4 g_wfrag[NKSG * NTILE * 32];

// =====================================================================
// Helpers
// =====================================================================
__device__ __forceinline__ uint32_t smem_u32(const void* p) {
    uint32_t a;
    asm("{ .reg .u64 t; cvta.to.shared.u64 t, %1; cvt.u32.u64 %0, t; }"
        : "=r"(a) : "l"(p));
    return a;
}
__device__ __forceinline__ void ldsm4(uint32_t addr, uint32_t* r) {
    asm volatile("ldmatrix.sync.aligned.m8n8.x4.shared.b16 {%0,%1,%2,%3}, [%4];"
                 : "=r"(r[0]), "=r"(r[1]), "=r"(r[2]), "=r"(r[3]) : "r"(addr));
}
__device__ __forceinline__ void mma16816(float* c, const uint32_t* a,
                                         uint32_t b0, uint32_t b1) {
    asm volatile("mma.sync.aligned.m16n8k16.row.col.f32.bf16.bf16.f32 "
                 "{%0,%1,%2,%3}, {%4,%5,%6,%7}, {%8,%9}, {%0,%1,%2,%3};"
                 : "+f"(c[0]), "+f"(c[1]), "+f"(c[2]), "+f"(c[3])
                 : "r"(a[0]), "r"(a[1]), "r"(a[2]), "r"(a[3]),
                   "r"(b0), "r"(b1));
}
__device__ __forceinline__ void split_pack(float x0, float x1,
                                           unsigned& wh, unsigned& wl) {
    __nv_bfloat16 h0 = __float2bfloat16_rn(x0);
    __nv_bfloat16 h1 = __float2bfloat16_rn(x1);
    float r0 = x0 - __bfloat162float(h0);
    float r1 = x1 - __bfloat162float(h1);
    __nv_bfloat16 l0 = __float2bfloat16_rn(r0);
    __nv_bfloat16 l1 = __float2bfloat16_rn(r1);
    wh = ((unsigned)__bfloat16_as_ushort(h1) << 16) | __bfloat16_as_ushort(h0);
    wl = ((unsigned)__bfloat16_as_ushort(l1) << 16) | __bfloat16_as_ushort(l0);
}
__device__ __forceinline__ void bar_pair(int pair) {
    asm volatile("bar.sync %0, 64;" :: "r"(1 + pair) : "memory");
}

// =====================================================================
// Kernel 1: weight fragment prep only (small, fast)
// =====================================================================
#define PREP_ITEMS (NKSG * NTILE * 32)          // 22464
#define PREP_BLOCKS ((PREP_ITEMS + 255) / 256)  // 88

__global__ __launch_bounds__(256, 1) void prep_kernel(
    const float* __restrict__ w0,
    const float* __restrict__ w1,
    const float* __restrict__ w2)
{
    const int g = blockIdx.x * 256 + threadIdx.x;
    if (g >= PREP_ITEMS) return;
    const int ksg   = g / (NTILE * 32);
    const int rem   = g - ksg * (NTILE * 32);
    const int ntile = rem >> 5;
    const int lane  = rem & 31;
    const int l  = (ksg == 0) ? 0 : (ksg <= 13) ? 1 : 2;
    const int s  = (ksg == 0) ? 0 : (ksg <= 13) ? (ksg - 1) : (ksg - 14);
    const int Kl = (l == 0) ? EMB : HID;
    const float* W = (l == 0) ? w0 : (l == 1) ? w1 : w2;

    const int n  = ntile * 8 + (lane >> 2);
    const int k0 = s * 16 + (lane & 3) * 2;

    float e0 = 0.f, e1 = 0.f, e2 = 0.f, e3 = 0.f;
    if (n < HID) {
        if (k0     < Kl) e0 = __ldg(W + (size_t)k0       * HID + n);
        if (k0 + 1 < Kl) e1 = __ldg(W + (size_t)(k0 + 1) * HID + n);
        if (k0 + 8 < Kl) e2 = __ldg(W + (size_t)(k0 + 8) * HID + n);
        if (k0 + 9 < Kl) e3 = __ldg(W + (size_t)(k0 + 9) * HID + n);
    }
    uint4 o;
    split_pack(e0, e1, o.x, o.z);
    split_pack(e2, e3, o.y, o.w);
    g_wfrag[g] = o;
}

// =====================================================================
// Kernel 2: fused embed + FM + split-bf16 mma.sync MLP + sigmoid.
// 64 rows/CTA, 256 threads (4 independent 64-thread pairs), 2 CTAs/SM.
// R11 MLP structure: 13 n8-tiles per warp (full n-half), ldsm once per
// kstep, single in-place epilogue per layer. Float4 embed gather.
// =====================================================================
#define NTH2 256
#define ROWS 64
#define APB  464                 // As row pitch in bytes (208 bf16 + pad)
#define AS_H 0
#define AS_L (ROWS * APB)                    // 29696
#define BIAS_O (2 * ROWS * APB)              // 59392
#define RSUM_O (BIAS_O + 3 * NPAD * 4)       // 61888
#define LR_O   (RSUM_O + ROWS * 4)           // 62144
#define SMEM_TOT (LR_O + ROWS * 4)           // 62400

__global__ __launch_bounds__(NTH2, 2) void nfm_fused_kernel(
    const int*   __restrict__ ids,
    const float* __restrict__ vals,
    const float* __restrict__ w,
    const float* __restrict__ v,
    const float* __restrict__ b0,
    const float* __restrict__ b1,
    const float* __restrict__ b2,
    const float* __restrict__ bglob,
    float*       __restrict__ out)
{
    extern __shared__ char smem[];
    const uint32_t SB = smem_u32(smem);
    float* bias_s = (float*)(smem + BIAS_O);
    float* rsum_s = (float*)(smem + RSUM_O);
    float* lr_s   = (float*)(smem + LR_O);

    const int tid   = threadIdx.x;
    const int wid   = tid >> 5;
    const int lane  = tid & 31;
    const int pair  = wid >> 1;              // 0..3
    const int nhalf = wid & 1;
    const int nbase = nhalf * 104;
    const int row0  = blockIdx.x * ROWS;

    // ---- init: bias + rsum (CTA-wide, once) ----
    for (int i = tid; i < 3 * NPAD; i += NTH2) {
        const int l = i / NPAD, n = i - l * NPAD;
        const float* bp = (l == 0) ? b0 : (l == 1) ? b1 : b2;
        bias_s[i] = (n < HID) ? __ldg(bp + n) : 0.f;
    }
    if (tid < ROWS) rsum_s[tid] = 0.f;
    __syncthreads();        // the only CTA-wide barrier

    // ---- fused embedding gather + FM: 4 lanes per row (lane = e-quad) ----
    {
        const int r8    = lane >> 2;         // 0..7 row within warp
        const int equad = lane & 3;          // e-quad 0..3
        const int r     = pair * 16 + nhalf * 8 + r8;
        const int gr    = row0 + r;
        const int*   idp = ids  + gr * NFEAT;
        const float* vp  = vals + gr * NFEAT;

        float4 xv = make_float4(0.f, 0.f, 0.f, 0.f);
        float4 x2 = make_float4(0.f, 0.f, 0.f, 0.f);
        float  lrw = 0.f;
#pragma unroll 13
        for (int f = 0; f < NFEAT; ++f) {
            const int   id  = __ldg(idp + f);
            const float val = __ldg(vp + f);
            const float4 ve = __ldg((const float4*)(v + (size_t)id * EMB) + equad);
            const float t0 = val * ve.x, t1 = val * ve.y;
            const float t2 = val * ve.z, t3 = val * ve.w;
            xv.x += t0; xv.y += t1; xv.z += t2; xv.w += t3;
            x2.x += t0 * t0; x2.y += t1 * t1;
            x2.z += t2 * t2; x2.w += t3 * t3;
            if (equad == 0) lrw += __ldg(w + id) * val;
        }
        const float fm0 = 0.5f * (xv.x * xv.x - x2.x);
        const float fm1 = 0.5f * (xv.y * xv.y - x2.y);
        const float fm2 = 0.5f * (xv.z * xv.z - x2.z);
        const float fm3 = 0.5f * (xv.w * xv.w - x2.w);
        unsigned h0, l0, h1, l1;
        split_pack(fm0, fm1, h0, l0);
        split_pack(fm2, fm3, h1, l1);
        *(uint2*)(smem + AS_H + r * APB + equad * 8) = make_uint2(h0, h1);
        *(uint2*)(smem + AS_L + r * APB + equad * 8) = make_uint2(l0, l1);
        if (equad == 0) lr_s[r] = lrw;
    }
    bar_pair(pair);          // this pair's 16 rows of As are ready

    // ---- MLP: R11 structure (13 tiles/warp, one epilogue per layer) ----
    float acc[13][4];
    float rs1 = 0.f, rs2 = 0.f;

    const uint32_t arow  = (uint32_t)(pair * 16 + (lane & 15));
    const uint32_t akofs = (uint32_t)((lane >> 4) << 3);
    const uint32_t aHbase = SB + AS_H + arow * APB;
    const uint32_t aLbase = SB + AS_L + arow * APB;

#pragma unroll 1
    for (int l = 0; l < 3; ++l) {
        const int ksteps = (l == 0) ? 1 : 13;
        const int ksbase = (l == 0) ? 0 : (l == 1) ? 1 : 14;

#pragma unroll
        for (int t = 0; t < 13; ++t)
#pragma unroll
            for (int q = 0; q < 4; ++q) acc[t][q] = 0.f;

#pragma unroll 1
        for (int ks = 0; ks < ksteps; ++ks) {
            const uint32_t kA = (uint32_t)(ks * 16);
            uint32_t ah[4], al[4];
            ldsm4(aHbase + (kA + akofs) * 2, ah);
            ldsm4(aLbase + (kA + akofs) * 2, al);
            const uint4* bp = g_wfrag
                + ((size_t)(ksbase + ks) * NTILE + nhalf * 13) * 32 + lane;
#pragma unroll
            for (int nt = 0; nt < 13; ++nt) {
                const uint4 f = __ldg(bp + nt * 32);
                mma16816(acc[nt], ah, f.x, f.y);   // A_hi * B_hi
                mma16816(acc[nt], ah, f.z, f.w);   // A_hi * B_lo
                mma16816(acc[nt], al, f.x, f.y);   // A_lo * B_hi
            }
        }

        if (l < 2) {
            bar_pair(pair);  // both warps of pair done reading As
            const int r1 = pair * 16 + (lane >> 2);
#pragma unroll
            for (int nt = 0; nt < 13; ++nt) {
                const int n = nbase + nt * 8 + 2 * (lane & 3);
                const float bb0 = bias_s[l * NPAD + n];
                const float bb1 = bias_s[l * NPAD + n + 1];
                unsigned wh, wl;
                split_pack(fmaxf(acc[nt][0] + bb0, 0.f),
                           fmaxf(acc[nt][1] + bb1, 0.f), wh, wl);
                *(unsigned*)(smem + AS_H + r1 * APB + 2 * n) = wh;
                *(unsigned*)(smem + AS_L + r1 * APB + 2 * n) = wl;
                split_pack(fmaxf(acc[nt][2] + bb0, 0.f),
                           fmaxf(acc[nt][3] + bb1, 0.f), wh, wl);
                *(unsigned*)(smem + AS_H + (r1 + 8) * APB + 2 * n) = wh;
                *(unsigned*)(smem + AS_L + (r1 + 8) * APB + 2 * n) = wl;
            }
            bar_pair(pair);  // writes visible before next layer's reads
        } else {
#pragma unroll
            for (int nt = 0; nt < 13; ++nt) {
                const int n = nbase + nt * 8 + 2 * (lane & 3);
                const float bb0 = bias_s[2 * NPAD + n];
                const float bb1 = bias_s[2 * NPAD + n + 1];
                rs1 += fmaxf(acc[nt][0] + bb0, 0.f) + fmaxf(acc[nt][1] + bb1, 0.f);
                rs2 += fmaxf(acc[nt][2] + bb0, 0.f) + fmaxf(acc[nt][3] + bb1, 0.f);
            }
        }
    }

    // ---- row sums: 4-lane shfl reduce, pair-shared atomics, pair barrier ----
    rs1 += __shfl_xor_sync(0xffffffffu, rs1, 1);
    rs1 += __shfl_xor_sync(0xffffffffu, rs1, 2);
    rs2 += __shfl_xor_sync(0xffffffffu, rs2, 1);
    rs2 += __shfl_xor_sync(0xffffffffu, rs2, 2);
    if ((lane & 3) == 0) {
        const int r1 = pair * 16 + (lane >> 2);
        atomicAdd(&rsum_s[r1],     rs1);
        atomicAdd(&rsum_s[r1 + 8], rs2);
    }
    bar_pair(pair);

    if (nhalf == 0 && lane < 16) {
        const int r  = pair * 16 + lane;
        const int gr = row0 + r;
        const float x = lr_s[r] + __ldg(bglob) + rsum_s[r];
        out[gr] = 1.f / (1.f + expf(-x));
    }
}

// =====================================================================
// Launch
// =====================================================================
extern "C" void kernel_launch(void* const* d_in, const int* in_sizes, int n_in,
                              void* d_out, int out_size)
{
    const int*   feat_ids  = (const int*)  d_in[0];
    const float* feat_vals = (const float*)d_in[1];
    const float* w         = (const float*)d_in[2];
    const float* v         = (const float*)d_in[3];
    const float* b         = (const float*)d_in[4];
    const float* w0        = (const float*)d_in[5];
    const float* b0        = (const float*)d_in[6];
    const float* w1        = (const float*)d_in[7];
    const float* b1        = (const float*)d_in[8];
    const float* w2        = (const float*)d_in[9];
    const float* b2        = (const float*)d_in[10];
    float* out = (float*)d_out;

    prep_kernel<<<PREP_BLOCKS, 256>>>(w0, w1, w2);

    static bool attr_set = false;
    if (!attr_set) {
        cudaFuncSetAttribute(nfm_fused_kernel,
                             cudaFuncAttributeMaxDynamicSharedMemorySize,
                             SMEM_TOT);
        attr_set = true;
    }
    nfm_fused_kernel<<<BATCH / ROWS, NTH2, SMEM_TOT>>>(
        feat_ids, feat_vals, w, v, b0, b1, b2, b, out);
}

// round 14
// speedup vs baseline: 1.2183x; 1.0077x over previous
#include <cuda_runtime.h>
#include <cuda_bf16.h>
#include <math.h>
#include <stdint.h>

// ---------------- Problem constants ----------------
#define BATCH 16384
#define NFEAT 39
#define EMB   16
#define HID   200
#define NPAD  208           // padded N (and K) for 16/8 tiling
#define NKSG  27            // total ksteps: L0:1, L1:13, L2:13
#define NTILE 26            // n8 tiles per layer

// ---------------- Scratch ----------------
// Weights pre-packed in mma fragment order:
// [ksg (27)][ntile (26)][lane (32)] x uint4 {bh0, bh1, bl0, bl1}
__device__ uint4 g_wfrag[NKSG * NTILE * 32];

// =====================================================================
// Helpers
// =====================================================================
__device__ __forceinline__ uint32_t smem_u32(const void* p) {
    uint32_t a;
    asm("{ .reg .u64 t; cvta.to.shared.u64 t, %1; cvt.u32.u64 %0, t; }"
        : "=r"(a) : "l"(p));
    return a;
}
__device__ __forceinline__ void ldsm4(uint32_t addr, uint32_t* r) {
    asm volatile("ldmatrix.sync.aligned.m8n8.x4.shared.b16 {%0,%1,%2,%3}, [%4];"
                 : "=r"(r[0]), "=r"(r[1]), "=r"(r[2]), "=r"(r[3]) : "r"(addr));
}
__device__ __forceinline__ void mma16816(float* c, const uint32_t* a,
                                         uint32_t b0, uint32_t b1) {
    asm volatile("mma.sync.aligned.m16n8k16.row.col.f32.bf16.bf16.f32 "
                 "{%0,%1,%2,%3}, {%4,%5,%6,%7}, {%8,%9}, {%0,%1,%2,%3};"
                 : "+f"(c[0]), "+f"(c[1]), "+f"(c[2]), "+f"(c[3])
                 : "r"(a[0]), "r"(a[1]), "r"(a[2]), "r"(a[3]),
                   "r"(b0), "r"(b1));
}
__device__ __forceinline__ void split_pack(float x0, float x1,
                                           unsigned& wh, unsigned& wl) {
    __nv_bfloat16 h0 = __float2bfloat16_rn(x0);
    __nv_bfloat16 h1 = __float2bfloat16_rn(x1);
    float r0 = x0 - __bfloat162float(h0);
    float r1 = x1 - __bfloat162float(h1);
    __nv_bfloat16 l0 = __float2bfloat16_rn(r0);
    __nv_bfloat16 l1 = __float2bfloat16_rn(r1);
    wh = ((unsigned)__bfloat16_as_ushort(h1) << 16) | __bfloat16_as_ushort(h0);
    wl = ((unsigned)__bfloat16_as_ushort(l1) << 16) | __bfloat16_as_ushort(l0);
}
__device__ __forceinline__ void bar_grp(int grp) {
    asm volatile("bar.sync %0, 128;" :: "r"(1 + grp) : "memory");
}

// =====================================================================
// Kernel 1: weight fragment prep only (small, fast)
// =====================================================================
#define PREP_ITEMS (NKSG * NTILE * 32)          // 22464
#define PREP_BLOCKS ((PREP_ITEMS + 255) / 256)  // 88

__global__ __launch_bounds__(256, 1) void prep_kernel(
    const float* __restrict__ w0,
    const float* __restrict__ w1,
    const float* __restrict__ w2)
{
    const int g = blockIdx.x * 256 + threadIdx.x;
    if (g >= PREP_ITEMS) return;
    const int ksg   = g / (NTILE * 32);
    const int rem   = g - ksg * (NTILE * 32);
    const int ntile = rem >> 5;
    const int lane  = rem & 31;
    const int l  = (ksg == 0) ? 0 : (ksg <= 13) ? 1 : 2;
    const int s  = (ksg == 0) ? 0 : (ksg <= 13) ? (ksg - 1) : (ksg - 14);
    const int Kl = (l == 0) ? EMB : HID;
    const float* W = (l == 0) ? w0 : (l == 1) ? w1 : w2;

    const int n  = ntile * 8 + (lane >> 2);
    const int k0 = s * 16 + (lane & 3) * 2;

    float e0 = 0.f, e1 = 0.f, e2 = 0.f, e3 = 0.f;
    if (n < HID) {
        if (k0     < Kl) e0 = __ldg(W + (size_t)k0       * HID + n);
        if (k0 + 1 < Kl) e1 = __ldg(W + (size_t)(k0 + 1) * HID + n);
        if (k0 + 8 < Kl) e2 = __ldg(W + (size_t)(k0 + 8) * HID + n);
        if (k0 + 9 < Kl) e3 = __ldg(W + (size_t)(k0 + 9) * HID + n);
    }
    uint4 o;
    split_pack(e0, e1, o.x, o.z);
    split_pack(e2, e3, o.y, o.w);
    g_wfrag[g] = o;
}

// =====================================================================
// Kernel 2: fused embed + FM + split-bf16 mma.sync MLP + sigmoid.
// 64 rows/CTA, 256 threads, 2 CTAs/SM.
// Warp tile: 32 rows (2 m16) x QN n8-tiles (quarters {7,7,6,6}).
// Each B fragment feeds 6 MMAs (2x reuse vs R13). 2 row-groups per
// CTA sync via 128-thread named barriers.
// =====================================================================
#define NTH2 256
#define ROWS 64
#define APB  464                 // As row pitch in bytes (208 bf16 + pad)
#define AS_H 0
#define AS_L (ROWS * APB)                    // 29696
#define BIAS_O (2 * ROWS * APB)              // 59392
#define RSUM_O (BIAS_O + 3 * NPAD * 4)       // 61888
#define LR_O   (RSUM_O + ROWS * 4)           // 62144
#define SMEM_TOT (LR_O + ROWS * 4)           // 62400

template<int QN>
__device__ __forceinline__ void mlp_body(
    char* smem, const uint32_t SB,
    const float* __restrict__ bias_s, float* __restrict__ rsum_s,
    const int rowgrp, const int qtile0, const int lane)
{
    float acc[2][QN][4];
    float rs[2][2] = {{0.f, 0.f}, {0.f, 0.f}};

    const uint32_t arow  = (uint32_t)(rowgrp * 32 + (lane & 15));
    const uint32_t akofs = (uint32_t)((lane >> 4) << 3);
    const uint32_t aH0 = SB + AS_H + arow * APB;
    const uint32_t aL0 = SB + AS_L + arow * APB;

#pragma unroll 1
    for (int l = 0; l < 3; ++l) {
        const int ksteps = (l == 0) ? 1 : 13;
        const int ksbase = (l == 0) ? 0 : (l == 1) ? 1 : 14;
        const float* bias = bias_s + l * NPAD;

#pragma unroll
        for (int m = 0; m < 2; ++m)
#pragma unroll
            for (int t = 0; t < QN; ++t)
#pragma unroll
                for (int q = 0; q < 4; ++q) acc[m][t][q] = 0.f;

#pragma unroll 1
        for (int ks = 0; ks < ksteps; ++ks) {
            const uint32_t ko = (uint32_t)(ks * 16) + akofs;
            uint32_t ah0[4], al0[4], ah1[4], al1[4];
            ldsm4(aH0 + ko * 2, ah0);
            ldsm4(aL0 + ko * 2, al0);
            ldsm4(aH0 + 16 * APB + ko * 2, ah1);
            ldsm4(aL0 + 16 * APB + ko * 2, al1);
            const uint4* bp = g_wfrag
                + ((size_t)(ksbase + ks) * NTILE + qtile0) * 32 + lane;
#pragma unroll
            for (int nt = 0; nt < QN; ++nt) {
                const uint4 f = __ldg(bp + nt * 32);
                mma16816(acc[0][nt], ah0, f.x, f.y);
                mma16816(acc[0][nt], ah0, f.z, f.w);
                mma16816(acc[0][nt], al0, f.x, f.y);
                mma16816(acc[1][nt], ah1, f.x, f.y);
                mma16816(acc[1][nt], ah1, f.z, f.w);
                mma16816(acc[1][nt], al1, f.x, f.y);
            }
        }

        if (l < 2) {
            bar_grp(rowgrp);     // all 4 warps of group done reading As
#pragma unroll
            for (int m = 0; m < 2; ++m) {
                const int r1 = rowgrp * 32 + m * 16 + (lane >> 2);
#pragma unroll
                for (int nt = 0; nt < QN; ++nt) {
                    const int n = (qtile0 + nt) * 8 + 2 * (lane & 3);
                    const float bb0 = bias[n];
                    const float bb1 = bias[n + 1];
                    unsigned wh, wl;
                    split_pack(fmaxf(acc[m][nt][0] + bb0, 0.f),
                               fmaxf(acc[m][nt][1] + bb1, 0.f), wh, wl);
                    *(unsigned*)(smem + AS_H + r1 * APB + 2 * n) = wh;
                    *(unsigned*)(smem + AS_L + r1 * APB + 2 * n) = wl;
                    split_pack(fmaxf(acc[m][nt][2] + bb0, 0.f),
                               fmaxf(acc[m][nt][3] + bb1, 0.f), wh, wl);
                    *(unsigned*)(smem + AS_H + (r1 + 8) * APB + 2 * n) = wh;
                    *(unsigned*)(smem + AS_L + (r1 + 8) * APB + 2 * n) = wl;
                }
            }
            bar_grp(rowgrp);     // writes visible before next layer's reads
        } else {
#pragma unroll
            for (int m = 0; m < 2; ++m)
#pragma unroll
                for (int nt = 0; nt < QN; ++nt) {
                    const int n = (qtile0 + nt) * 8 + 2 * (lane & 3);
                    const float bb0 = bias[n];
                    const float bb1 = bias[n + 1];
                    rs[m][0] += fmaxf(acc[m][nt][0] + bb0, 0.f)
                              + fmaxf(acc[m][nt][1] + bb1, 0.f);
                    rs[m][1] += fmaxf(acc[m][nt][2] + bb0, 0.f)
                              + fmaxf(acc[m][nt][3] + bb1, 0.f);
                }
        }
    }

    // row sums: 4-lane shfl reduce then shared atomics
#pragma unroll
    for (int m = 0; m < 2; ++m)
#pragma unroll
        for (int h = 0; h < 2; ++h) {
            rs[m][h] += __shfl_xor_sync(0xffffffffu, rs[m][h], 1);
            rs[m][h] += __shfl_xor_sync(0xffffffffu, rs[m][h], 2);
        }
    if ((lane & 3) == 0) {
        const int rb = rowgrp * 32 + (lane >> 2);
        atomicAdd(&rsum_s[rb],          rs[0][0]);
        atomicAdd(&rsum_s[rb + 8],      rs[0][1]);
        atomicAdd(&rsum_s[rb + 16],     rs[1][0]);
        atomicAdd(&rsum_s[rb + 24],     rs[1][1]);
    }
}

__global__ __launch_bounds__(NTH2, 2) void nfm_fused_kernel(
    const int*   __restrict__ ids,
    const float* __restrict__ vals,
    const float* __restrict__ w,
    const float* __restrict__ v,
    const float* __restrict__ b0,
    const float* __restrict__ b1,
    const float* __restrict__ b2,
    const float* __restrict__ bglob,
    float*       __restrict__ out)
{
    extern __shared__ char smem[];
    const uint32_t SB = smem_u32(smem);
    float* bias_s = (float*)(smem + BIAS_O);
    float* rsum_s = (float*)(smem + RSUM_O);
    float* lr_s   = (float*)(smem + LR_O);

    const int tid    = threadIdx.x;
    const int wid    = tid >> 5;
    const int lane   = tid & 31;
    const int rowgrp = wid >> 2;             // 0..1 (32 rows each)
    const int nq     = wid & 3;              // n-quarter
    const int row0   = blockIdx.x * ROWS;

    // quarter tile bases/counts: {7,7,6,6} tiles -> bases {0,7,14,20}
    const int qtile0 = (nq == 0) ? 0 : (nq == 1) ? 7 : (nq == 2) ? 14 : 20;

    // ---- init: bias + rsum (CTA-wide, once) ----
    for (int i = tid; i < 3 * NPAD; i += NTH2) {
        const int l = i / NPAD, n = i - l * NPAD;
        const float* bp = (l == 0) ? b0 : (l == 1) ? b1 : b2;
        bias_s[i] = (n < HID) ? __ldg(bp + n) : 0.f;
    }
    if (tid < ROWS) rsum_s[tid] = 0.f;
    __syncthreads();        // the only CTA-wide barrier

    // ---- fused embedding gather + FM: 4 lanes per row, one pass ----
    {
        const int t128  = nq * 32 + lane;    // 0..127 within row-group
        const int r     = rowgrp * 32 + (t128 >> 2);
        const int equad = t128 & 3;
        const int gr    = row0 + r;
        const int*   idp = ids  + gr * NFEAT;
        const float* vp  = vals + gr * NFEAT;

        float4 xv = make_float4(0.f, 0.f, 0.f, 0.f);
        float4 x2 = make_float4(0.f, 0.f, 0.f, 0.f);
        float  lrw = 0.f;
#pragma unroll 13
        for (int f = 0; f < NFEAT; ++f) {
            const int   id  = __ldg(idp + f);
            const float val = __ldg(vp + f);
            const float4 ve = __ldg((const float4*)(v + (size_t)id * EMB) + equad);
            const float t0 = val * ve.x, t1 = val * ve.y;
            const float t2 = val * ve.z, t3 = val * ve.w;
            xv.x += t0; xv.y += t1; xv.z += t2; xv.w += t3;
            x2.x += t0 * t0; x2.y += t1 * t1;
            x2.z += t2 * t2; x2.w += t3 * t3;
            if (equad == 0) lrw += __ldg(w + id) * val;
        }
        const float fm0 = 0.5f * (xv.x * xv.x - x2.x);
        const float fm1 = 0.5f * (xv.y * xv.y - x2.y);
        const float fm2 = 0.5f * (xv.z * xv.z - x2.z);
        const float fm3 = 0.5f * (xv.w * xv.w - x2.w);
        unsigned h0, l0, h1, l1;
        split_pack(fm0, fm1, h0, l0);
        split_pack(fm2, fm3, h1, l1);
        *(uint2*)(smem + AS_H + r * APB + equad * 8) = make_uint2(h0, h1);
        *(uint2*)(smem + AS_L + r * APB + equad * 8) = make_uint2(l0, l1);
        if (equad == 0) lr_s[r] = lrw;
    }
    bar_grp(rowgrp);         // this group's 32 rows of As are ready

    // ---- MLP ----
    if (nq < 2) mlp_body<7>(smem, SB, bias_s, rsum_s, rowgrp, qtile0, lane);
    else        mlp_body<6>(smem, SB, bias_s, rsum_s, rowgrp, qtile0, lane);

    bar_grp(rowgrp);

    if (nq == 0) {
        const int r  = rowgrp * 32 + lane;
        const int gr = row0 + r;
        const float x = lr_s[r] + __ldg(bglob) + rsum_s[r];
        out[gr] = 1.f / (1.f + expf(-x));
    }
}

// =====================================================================
// Launch
// =====================================================================
extern "C" void kernel_launch(void* const* d_in, const int* in_sizes, int n_in,
                              void* d_out, int out_size)
{
    const int*   feat_ids  = (const int*)  d_in[0];
    const float* feat_vals = (const float*)d_in[1];
    const float* w         = (const float*)d_in[2];
    const float* v         = (const float*)d_in[3];
    const float* b         = (const float*)d_in[4];
    const float* w0        = (const float*)d_in[5];
    const float* b0        = (const float*)d_in[6];
    const float* w1        = (const float*)d_in[7];
    const float* b1        = (const float*)d_in[8];
    const float* w2        = (const float*)d_in[9];
    const float* b2        = (const float*)d_in[10];
    float* out = (float*)d_out;

    prep_kernel<<<PREP_BLOCKS, 256>>>(w0, w1, w2);

    static bool attr_set = false;
    if (!attr_set) {
        cudaFuncSetAttribute(nfm_fused_kernel,
                             cudaFuncAttributeMaxDynamicSharedMemorySize,
                             SMEM_TOT);
        attr_set = true;
    }
    nfm_fused_kernel<<<BATCH / ROWS, NTH2, SMEM_TOT>>>(
        feat_ids, feat_vals, w, v, b0, b1, b2, b, out);
}